// round 1
// baseline (speedup 1.0000x reference)
#include <cuda_runtime.h>

#define Bn   16
#define An   3
#define Cn   80
#define Hn   76
#define Wn   76
#define Tn   50
#define HWn  (Hn*Wn)          // 5776
#define AHWn (An*HWn)         // 17328
#define OOBn (Bn*An*HWn)      // 277248
#define NT   (Bn*Tn)          // 800
#define NCH  (An*(5+Cn))      // 255
#define NBITS ((OOBn+31)/32)  // 8664

__constant__ float c_aw[3] = {1.25f, 2.0f, 4.125f};
__constant__ float c_ah[3] = {1.625f, 3.75f, 2.875f};

struct Scratch {
    // acc: 0=x 1=y 2=w 3=h 4=conf_masked 5=cls 6=conf_all 7=conf_at_noobj_zero
    double acc[8];
    int n_m;
    int n_zero;
    int   t_idx[NT];
    float t_tx[NT], t_ty[NT], t_tw[NT], t_th[NT];
    int   t_cls[NT];
    unsigned int bits[NBITS];
};
__device__ Scratch g;

__device__ __forceinline__ float sigm(float z) { return 1.0f / (1.0f + expf(-z)); }
__device__ __forceinline__ float clog(float p) { return fmaxf(logf(p), -100.0f); }

// ---------------------------------------------------------------------------
// K1: single block. Zero scratch, build per-target records, noobj distinct
// cells (bitset dedup), winner dedup (last-target-wins), masked-cell losses.
// ---------------------------------------------------------------------------
__global__ void k_targets(const float* __restrict__ in, const float* __restrict__ tg)
{
    __shared__ int s_idx[NT];
    __shared__ unsigned char s_cls[NT];
    const int tid = threadIdx.x;
    const int NB  = blockDim.x;

    for (int i = tid; i < NBITS; i += NB) g.bits[i] = 0u;
    if (tid < 8)  g.acc[tid] = 0.0;
    if (tid == 8) g.n_m = 0;
    if (tid == 9) g.n_zero = 0;
    __syncthreads();

    // phase 1: per-target records + noobj flags
    for (int i = tid; i < NT; i += NB) {
        const float* t = tg + i * 5;
        float cls = t[0], cx = t[1], cy = t[2], cw = t[3], ch = t[4];
        bool valid = ((cls + cx + cy + cw + ch) != 0.0f);
        float gx = cx * (float)Wn, gy = cy * (float)Hn;
        float gw = cw * (float)Wn, gh = ch * (float)Hn;
        int gi = (int)gx, gj = (int)gy;
        float a1 = (gw + 1.0f) * (gh + 1.0f);
        float iou[3];
        #pragma unroll
        for (int a = 0; a < 3; a++) {
            float inter = fmaxf(fminf(gw, c_aw[a]) + 1.0f, 0.0f) *
                          fmaxf(fminf(gh, c_ah[a]) + 1.0f, 0.0f);
            float a2 = (c_aw[a] + 1.0f) * (c_ah[a] + 1.0f);
            iou[a] = inter / (a1 + a2 - inter + 1e-16f);
        }
        int best = 0;
        if (iou[1] > iou[0])    best = 1;
        if (iou[2] > iou[best]) best = 2;
        bool ok = valid && (gj < Hn) && (gi < Wn);
        int b = i / Tn;
        long cell = (((long)(b * An + best)) * Hn + gj) * Wn + gi;
        int idx = (ok && cell >= 0 && cell < OOBn) ? (int)cell : -1;
        g.t_idx[i] = idx;
        s_idx[i]   = idx;
        g.t_tx[i]  = gx - (float)gi;
        g.t_ty[i]  = gy - (float)gj;
        g.t_tw[i]  = logf(gw / c_aw[best] + 1e-16f);
        g.t_th[i]  = logf(gh / c_ah[best] + 1e-16f);
        int ci = (int)cls;
        g.t_cls[i] = ci;
        s_cls[i]   = (unsigned char)ci;
        // noobj: each anchor with iou > 0.5 zeroes a cell; dedup via bitset
        #pragma unroll
        for (int a = 0; a < 3; a++) {
            if (valid && iou[a] > 0.5f) {
                long ni = (((long)(b * An + a)) * Hn + gj) * Wn + gi;
                if (ni >= 0 && ni < OOBn) {
                    int w = (int)(ni >> 5);
                    unsigned int bit = 1u << ((int)ni & 31);
                    unsigned int old = atomicOr(&g.bits[w], bit);
                    if (!(old & bit)) {
                        int bb  = (int)(ni / AHWn);
                        int rem = (int)(ni % AHWn);
                        int aa  = rem / HWn;
                        int hw  = rem % HWn;
                        float z = in[((size_t)bb * NCH + aa * 85 + 4) * HWn + hw];
                        float s = sigm(z);
                        float term = -clog(1.0f - s);
                        atomicAdd(&g.acc[7], (double)term);
                        atomicAdd(&g.n_zero, 1);
                    }
                }
            }
        }
    }
    __syncthreads();

    // phase 2: winner dedup (LAST flattened index wins) + masked-cell losses
    for (int i = tid; i < NT; i += NB) {
        int ci = s_idx[i];
        if (ci < 0) continue;
        bool win = true;
        for (int j = i + 1; j < NT; j++)
            if (s_idx[j] == ci) { win = false; break; }
        if (!win) continue;
        atomicAdd(&g.n_m, 1);

        int bb  = ci / AHWn;
        int rem = ci % AHWn;
        int aa  = rem / HWn;
        int hw  = rem % HWn;
        const float* base = in + ((size_t)bb * NCH + aa * 85) * HWn + hw;
        float x  = sigm(base[0 * HWn]);
        float y  = sigm(base[1 * HWn]);
        float wv = base[2 * HWn];
        float hv = base[3 * HWn];
        float cf = sigm(base[4 * HWn]);
        float tx = g.t_tx[i], ty = g.t_ty[i], tw = g.t_tw[i], th = g.t_th[i];

        float lxs = -(tx * clog(x) + (1.0f - tx) * clog(1.0f - x));
        float lys = -(ty * clog(y) + (1.0f - ty) * clog(1.0f - y));
        float lws = (wv - tw) * (wv - tw);
        float lhs = (hv - th) * (hv - th);
        float lcm = -clog(cf);

        // class union over ALL targets mapping to this cell (tcls sets 1.0 at
        // distinct flat indices cell*C+cls, so collisions OR their classes)
        unsigned int cm[3] = {0u, 0u, 0u};
        for (int j = 0; j < NT; j++)
            if (s_idx[j] == ci) { int c = s_cls[j]; cm[c >> 5] |= 1u << (c & 31); }

        float lcls = 0.0f;
        for (int c = 0; c < Cn; c++) {
            float pc = sigm(base[(5 + c) * HWn]);
            bool on = (cm[c >> 5] >> (c & 31)) & 1u;
            lcls += on ? (-clog(pc)) : (-clog(1.0f - pc));
        }

        atomicAdd(&g.acc[0], (double)lxs);
        atomicAdd(&g.acc[1], (double)lys);
        atomicAdd(&g.acc[2], (double)lws);
        atomicAdd(&g.acc[3], (double)lhs);
        atomicAdd(&g.acc[4], (double)lcm);
        atomicAdd(&g.acc[5], (double)lcls);
    }
}

// ---------------------------------------------------------------------------
// K2: dense no-object conf sum over ALL cells (noobj=0 contribution is
// subtracted in finalize via acc[7]). conf channel is contiguous per (b,a):
// float4-coalesced.
// ---------------------------------------------------------------------------
__global__ void k_confsum(const float* __restrict__ in)
{
    const int NV = OOBn / 4;       // 69312 float4s
    const int CQ = HWn / 4;        // 1444 float4 per (b,a) channel
    int t = blockIdx.x * blockDim.x + threadIdx.x;
    float local = 0.0f;
    if (t < NV) {
        int blk = t / CQ;          // 0..47  -> (b,a)
        int off = t % CQ;
        int bb = blk / An, aa = blk % An;
        const float4* p = (const float4*)(in + ((size_t)bb * NCH + aa * 85 + 4) * HWn);
        float4 v = p[off];
        local  = -clog(1.0f - sigm(v.x));
        local += -clog(1.0f - sigm(v.y));
        local += -clog(1.0f - sigm(v.z));
        local += -clog(1.0f - sigm(v.w));
    }
    #pragma unroll
    for (int o = 16; o; o >>= 1) local += __shfl_down_sync(0xFFFFFFFFu, local, o);
    __shared__ double ws[8];
    if ((threadIdx.x & 31) == 0) ws[threadIdx.x >> 5] = (double)local;
    __syncthreads();
    if (threadIdx.x == 0) {
        double s = 0.0;
        #pragma unroll
        for (int i = 0; i < 8; i++) s += ws[i];
        atomicAdd(&g.acc[6], s);
    }
}

// ---------------------------------------------------------------------------
// K3: finalize the 7 outputs
// ---------------------------------------------------------------------------
__global__ void k_final(float* __restrict__ out)
{
    double nm   = (double)g.n_m;
    double nnm  = (double)(OOBn - g.n_zero);
    double inv  = 1.0 / (double)OOBn;
    double lx   = g.acc[0] * inv / nm;
    double ly   = g.acc[1] * inv / nm;
    double lw   = g.acc[2] * inv / nm;
    double lh   = g.acc[3] * inv / nm;
    double lconf = g.acc[4] * inv / nm + 0.5 * ((g.acc[6] - g.acc[7]) * inv) / nnm;
    double lcls  = g.acc[5] / (nm * (double)Cn) / nm;
    double loss  = 2.5 * (lx + ly) + 2.5 * (lw + lh) + lconf + lcls;
    out[0] = (float)loss;
    out[1] = (float)lx;
    out[2] = (float)ly;
    out[3] = (float)lw;
    out[4] = (float)lh;
    out[5] = (float)lconf;
    out[6] = (float)lcls;
}

extern "C" void kernel_launch(void* const* d_in, const int* in_sizes, int n_in,
                              void* d_out, int out_size)
{
    const float* in = (const float*)d_in[0];
    const float* tg = (const float*)d_in[1];
    if (n_in >= 2 && in_sizes[0] < in_sizes[1]) {  // defensive: order by size
        in = (const float*)d_in[1];
        tg = (const float*)d_in[0];
    }
    k_targets<<<1, 256>>>(in, tg);
    const int NV = OOBn / 4;
    k_confsum<<<(NV + 255) / 256, 256>>>(in);
    k_final<<<1, 1>>>((float*)d_out);
}

// round 7
// speedup vs baseline: 187.5632x; 187.5632x over previous
#include <cuda_runtime.h>

#define Bn   16
#define An   3
#define Cn   80
#define Hn   76
#define Wn   76
#define Tn   50
#define HWn  (Hn*Wn)          // 5776
#define AHWn (An*HWn)         // 17328
#define OOBn (Bn*An*HWn)      // 277248
#define NT   (Bn*Tn)          // 800
#define NCH  (An*(5+Cn))      // 255
#define NBITS ((OOBn+31)/32)  // 8664
#define NV   (OOBn/4)         // 69312 float4 of conf
#define GRID 271              // ceil(NV/256)
#define NSLOT 10              // 0..5 losses, 6 conf_all, 7 conf_at_noobj0, 8 n_zero, 9 n_m

__constant__ float c_aw[3] = {1.25f, 2.0f, 4.125f};
__constant__ float c_ah[3] = {1.625f, 3.75f, 2.875f};

struct GMem {
    float part[GRID][NSLOT];
    int   ticket;
};
__device__ GMem g;   // ticket zero-initialized at module load; finalizer resets it

__device__ __forceinline__ float sigm(float z) { return 1.0f / (1.0f + expf(-z)); }
__device__ __forceinline__ float clog(float p) { return fmaxf(logf(p), -100.0f); }

__device__ __forceinline__ int target_record(const float* __restrict__ tg, int i,
                                             int* cls_out, float* tx, float* ty,
                                             float* tw, float* th, float* iou_out,
                                             int* gi_out, int* gj_out, bool* valid_out)
{
    const float* t = tg + i * 5;
    float cls = t[0], cx = t[1], cy = t[2], cw = t[3], ch = t[4];
    bool valid = ((cls + cx + cy + cw + ch) != 0.0f);
    float gx = cx * (float)Wn, gy = cy * (float)Hn;
    float gw = cw * (float)Wn, gh = ch * (float)Hn;
    int gi = (int)gx, gj = (int)gy;
    float a1 = (gw + 1.0f) * (gh + 1.0f);
    float iou[3];
    #pragma unroll
    for (int a = 0; a < 3; a++) {
        float inter = fmaxf(fminf(gw, c_aw[a]) + 1.0f, 0.0f) *
                      fmaxf(fminf(gh, c_ah[a]) + 1.0f, 0.0f);
        float a2 = (c_aw[a] + 1.0f) * (c_ah[a] + 1.0f);
        iou[a] = inter / (a1 + a2 - inter + 1e-16f);
    }
    int best = 0;
    if (iou[1] > iou[0])    best = 1;
    if (iou[2] > iou[best]) best = 2;
    bool ok = valid && (gj < Hn) && (gi < Wn);
    int b = i / Tn;
    long cell = (((long)(b * An + best)) * Hn + gj) * Wn + gi;
    int idx = (ok && cell >= 0 && cell < OOBn) ? (int)cell : -1;
    if (cls_out) *cls_out = (int)cls;
    if (tx) *tx = gx - (float)gi;
    if (ty) *ty = gy - (float)gj;
    if (tw) *tw = logf(gw / c_aw[best] + 1e-16f);
    if (th) *th = logf(gh / c_ah[best] + 1e-16f);
    if (iou_out) { iou_out[0] = iou[0]; iou_out[1] = iou[1]; iou_out[2] = iou[2]; }
    if (gi_out) *gi_out = gi;
    if (gj_out) *gj_out = gj;
    if (valid_out) *valid_out = valid;
    return idx;
}

__global__ void __launch_bounds__(256, 4)
yolo_fused(const float* __restrict__ in, const float* __restrict__ tg,
           float* __restrict__ out)
{
    __shared__ int           s_idx[NT];
    __shared__ unsigned char s_cls[NT];
    __shared__ unsigned int  s_bits[NBITS];   // only block 0 touches
    __shared__ float         s_acc[NSLOT];
    __shared__ int           s_last;
    __shared__ double        s_dacc[NSLOT];

    const int tid  = threadIdx.x;
    const int lane = tid & 31;
    const int wib  = tid >> 5;                 // warp in block (0..7)

    if (tid < NSLOT) s_acc[tid] = 0.0f;

    // --- per-target records (all blocks, redundant; trivial ALU) ---
    for (int i = tid; i < NT; i += 256) {
        int cls;
        int idx = target_record(tg, i, &cls, 0, 0, 0, 0, 0, 0, 0, 0);
        s_idx[i] = idx;
        s_cls[i] = (unsigned char)cls;
    }
    if (blockIdx.x == 0)
        for (int i = tid; i < NBITS; i += 256) s_bits[i] = 0u;
    __syncthreads();

    // --- dense conf sum slice: one float4 per thread ---
    {
        int t = blockIdx.x * 256 + tid;
        float local = 0.0f;
        if (t < NV) {
            const int CQ = HWn / 4;            // 1444
            int blk = t / CQ;                  // (b,a)
            int off = t - blk * CQ;
            int bb = blk / An, aa = blk - bb * An;
            const float4* p = (const float4*)(in + ((size_t)bb * NCH + aa * 85 + 4) * HWn);
            float4 v = p[off];
            local  = -clog(1.0f - sigm(v.x));
            local += -clog(1.0f - sigm(v.y));
            local += -clog(1.0f - sigm(v.z));
            local += -clog(1.0f - sigm(v.w));
        }
        #pragma unroll
        for (int o = 16; o; o >>= 1) local += __shfl_down_sync(0xFFFFFFFFu, local, o);
        if (lane == 0) atomicAdd(&s_acc[6], local);
    }

    // --- block 0: noobj distinct cells (bitset dedup) + conf at those cells ---
    if (blockIdx.x == 0) {
        for (int i = tid; i < NT; i += 256) {
            float iou[3]; int gi, gj; bool valid;
            target_record(tg, i, 0, 0, 0, 0, 0, iou, &gi, &gj, &valid);
            int b = i / Tn;
            #pragma unroll
            for (int a = 0; a < 3; a++) {
                if (valid && iou[a] > 0.5f) {
                    long ni = (((long)(b * An + a)) * Hn + gj) * Wn + gi;
                    if (ni >= 0 && ni < OOBn) {
                        int w = (int)(ni >> 5);
                        unsigned int bit = 1u << ((int)ni & 31);
                        unsigned int old = atomicOr(&s_bits[w], bit);
                        if (!(old & bit)) {
                            int bb  = (int)(ni / AHWn);
                            int rem = (int)(ni % AHWn);
                            int aa  = rem / HWn;
                            int hw  = rem % HWn;
                            float z = in[((size_t)bb * NCH + aa * 85 + 4) * HWn + hw];
                            atomicAdd(&s_acc[7], -clog(1.0f - sigm(z)));
                            atomicAdd(&s_acc[8], 1.0f);
                        }
                    }
                }
            }
        }
    }

    // --- winners: one warp per candidate target, grid-strided ---
    {
        const int NW = GRID * 8;               // total warps
        int gw = blockIdx.x * 8 + wib;
        for (int i = gw; i < NT; i += NW) {
            int ci = s_idx[i];
            if (ci < 0) continue;
            // last-index-wins dedup: any j>i with same idx disqualifies i
            bool dup = false;
            for (int j = i + 1 + lane; j < NT; j += 32)
                if (s_idx[j] == ci) { dup = true; break; }
            if (__any_sync(0xFFFFFFFFu, dup)) continue;

            // class union over all targets mapping to this cell
            unsigned int m0 = 0, m1 = 0, m2 = 0;
            for (int j = lane; j < NT; j += 32)
                if (s_idx[j] == ci) {
                    int c = s_cls[j];
                    if (c < 32) m0 |= 1u << c;
                    else if (c < 64) m1 |= 1u << (c - 32);
                    else m2 |= 1u << (c - 64);
                }
            #pragma unroll
            for (int o = 16; o; o >>= 1) {
                m0 |= __shfl_xor_sync(0xFFFFFFFFu, m0, o);
                m1 |= __shfl_xor_sync(0xFFFFFFFFu, m1, o);
                m2 |= __shfl_xor_sync(0xFFFFFFFFu, m2, o);
            }

            // regression targets only needed by lanes 0..4
            float tx = 0, ty = 0, tw = 0, th = 0;
            if (lane < 5) target_record(tg, i, 0, &tx, &ty, &tw, &th, 0, 0, 0, 0);

            int bb  = ci / AHWn;
            int rem = ci % AHWn;
            int aa  = rem / HWn;
            int hw  = rem % HWn;
            const float* base = in + ((size_t)bb * NCH + aa * 85) * HWn + hw;

            float lx = 0, ly = 0, lw = 0, lh = 0, lcm = 0, lcls = 0;
            for (int ch = lane; ch < 85; ch += 32) {
                float v = base[(size_t)ch * HWn];
                if (ch == 0)      { float p = sigm(v); lx = -(tx * clog(p) + (1.0f - tx) * clog(1.0f - p)); }
                else if (ch == 1) { float p = sigm(v); ly = -(ty * clog(p) + (1.0f - ty) * clog(1.0f - p)); }
                else if (ch == 2) { lw = (v - tw) * (v - tw); }
                else if (ch == 3) { lh = (v - th) * (v - th); }
                else if (ch == 4) { lcm = -clog(sigm(v)); }
                else {
                    int c = ch - 5;
                    bool on = (c < 32) ? ((m0 >> c) & 1u)
                            : (c < 64) ? ((m1 >> (c - 32)) & 1u)
                                       : ((m2 >> (c - 64)) & 1u);
                    float p = sigm(v);
                    lcls += on ? (-clog(p)) : (-clog(1.0f - p));
                }
            }
            #pragma unroll
            for (int o = 16; o; o >>= 1) {
                lx  += __shfl_down_sync(0xFFFFFFFFu, lx,  o);
                ly  += __shfl_down_sync(0xFFFFFFFFu, ly,  o);
                lw  += __shfl_down_sync(0xFFFFFFFFu, lw,  o);
                lh  += __shfl_down_sync(0xFFFFFFFFu, lh,  o);
                lcm += __shfl_down_sync(0xFFFFFFFFu, lcm, o);
                lcls+= __shfl_down_sync(0xFFFFFFFFu, lcls,o);
            }
            if (lane == 0) {
                atomicAdd(&s_acc[0], lx);
                atomicAdd(&s_acc[1], ly);
                atomicAdd(&s_acc[2], lw);
                atomicAdd(&s_acc[3], lh);
                atomicAdd(&s_acc[4], lcm);
                atomicAdd(&s_acc[5], lcls);
                atomicAdd(&s_acc[9], 1.0f);
            }
        }
    }
    __syncthreads();

    // --- publish block partials ---
    if (tid < NSLOT) g.part[blockIdx.x][tid] = s_acc[tid];
    __threadfence();
    __syncthreads();
    if (tid == 0) {
        int old = atomicAdd(&g.ticket, 1);
        s_last = (old == GRID - 1);
    }
    __syncthreads();

    // --- last block finalizes ---
    if (s_last) {
        __threadfence();   // acquire side: ensure partials of all blocks visible
        // FIX (R6 bug): 8 warps must cover all 10 slots — stride the slot loop.
        for (int slot = wib; slot < NSLOT; slot += 8) {
            double s = 0.0;
            for (int b = lane; b < GRID; b += 32) s += (double)g.part[b][slot];
            #pragma unroll
            for (int o = 16; o; o >>= 1)
                s += __shfl_down_sync(0xFFFFFFFFu, s, o);
            if (lane == 0) s_dacc[slot] = s;
        }
        __syncthreads();
        if (tid == 0) {
            double nm   = s_dacc[9];
            double nnm  = (double)OOBn - s_dacc[8];
            double inv  = 1.0 / (double)OOBn;
            double lx   = s_dacc[0] * inv / nm;
            double ly   = s_dacc[1] * inv / nm;
            double lw   = s_dacc[2] * inv / nm;
            double lh   = s_dacc[3] * inv / nm;
            double lconf = s_dacc[4] * inv / nm + 0.5 * ((s_dacc[6] - s_dacc[7]) * inv) / nnm;
            double lcls  = s_dacc[5] / (nm * (double)Cn) / nm;
            double loss  = 2.5 * (lx + ly) + 2.5 * (lw + lh) + lconf + lcls;
            out[0] = (float)loss;
            out[1] = (float)lx;
            out[2] = (float)ly;
            out[3] = (float)lw;
            out[4] = (float)lh;
            out[5] = (float)lconf;
            out[6] = (float)lcls;
            g.ticket = 0;   // reset for next graph replay
        }
    }
}

extern "C" void kernel_launch(void* const* d_in, const int* in_sizes, int n_in,
                              void* d_out, int out_size)
{
    const float* in = (const float*)d_in[0];
    const float* tg = (const float*)d_in[1];
    if (n_in >= 2 && in_sizes[0] < in_sizes[1]) {  // defensive: order by size
        in = (const float*)d_in[1];
        tg = (const float*)d_in[0];
    }
    yolo_fused<<<GRID, 256>>>(in, tg, (float*)d_out);
}